// round 1
// baseline (speedup 1.0000x reference)
#include <cuda_runtime.h>

// RSA_layer: B=64, U=W=128.
// Only output row i=127 is needed; softmax-constant terms (w_hj, bias) cancel.
// Per batch b:
//   f[j][u] = (u<127) ? state[b,j,u+1] : input[b,j]
//   q       = f[127]
//   d[j]    = q . f[j]
//   s[j][v] = (f @ w_hi)[j][v] + d[j]*w_dot[v]
//   out[b][u] = sum_j f[j][u] * softmax_j(s[j][u])
//
// Grid: 64 batches x 2 v-halves = 128 CTAs, 256 threads.
// Dynamic smem: fT[128][132] + w_s[128][68] + s_s[128][68] + q/d/wdot.

#define THREADS 256
#define FT_STRIDE 132
#define WS_STRIDE 68

static constexpr int SMEM_FLOATS = 128 * FT_STRIDE + 128 * WS_STRIDE * 2 + 128 + 128 + 64;
static constexpr int SMEM_BYTES = SMEM_FLOATS * 4;

__global__ __launch_bounds__(THREADS, 1)
void rsa_kernel(const float* __restrict__ input,
                const float* __restrict__ state,
                const float* __restrict__ w,
                float* __restrict__ out)
{
    extern __shared__ float sm[];

    const int b   = blockIdx.x >> 1;
    const int h   = blockIdx.x & 1;
    const int v0  = h * 64;           // global v/u offset of this CTA's half
    const int tid = threadIdx.x;

    float* fT     = sm;                          // [128 u][132] (col j)
    float* w_s    = fT  + 128 * FT_STRIDE;       // [128 u][68] (64 v cols)
    float* s_s    = w_s + 128 * WS_STRIDE;       // [128 j][68]
    float* q_s    = s_s + 128 * WS_STRIDE;       // [128]
    float* d_s    = q_s + 128;                   // [128]
    float* wdot_s = d_s + 128;                   // [64]

    const float* stateb = state + (size_t)b * 128 * 128;
    const float* inputb = input + b * 128;

    // ---- Phase 0: stage fT (transposed, shifted) and w_hi half ----
    #pragma unroll 4
    for (int idx = tid; idx < 128 * 128; idx += THREADS) {
        int j = idx >> 7, u = idx & 127;
        float val = (u < 127) ? stateb[j * 128 + u + 1] : inputb[j];
        fT[u * FT_STRIDE + j] = val;
    }
    #pragma unroll 4
    for (int idx = tid; idx < 128 * 64; idx += THREADS) {
        int u = idx >> 6, vl = idx & 63;
        w_s[u * WS_STRIDE + vl] = w[u * 128 + v0 + vl];
    }
    if (tid < 64) wdot_s[tid] = w[256 * 128 + v0 + tid];
    __syncthreads();

    // ---- Phase 1: q = f[127] ----
    if (tid < 128) q_s[tid] = fT[tid * FT_STRIDE + 127];
    __syncthreads();

    // ---- Phase 2: d[j] = q . f[j]  (thread j; conflict-free column reads) ----
    if (tid < 128) {
        float acc = 0.f;
        #pragma unroll 8
        for (int u = 0; u < 128; u++)
            acc += fT[u * FT_STRIDE + tid] * q_s[u];
        d_s[tid] = acc;
    }
    __syncthreads();

    // ---- Phase 3: s[j][v] = (f @ w_hi)[j][v] + d[j]*wdot[v] ----
    // 32x8 thread grid, each thread computes a 4(j) x 8(v) tile.
    const int ty  = tid >> 3;     // 0..31 -> j block
    const int tx  = tid & 7;      // 0..7  -> v block
    const int j0  = ty * 4;
    const int vl0 = tx * 8;

    float acc[4][8];
    #pragma unroll
    for (int a = 0; a < 4; a++)
        #pragma unroll
        for (int c = 0; c < 8; c++) acc[a][c] = 0.f;

    #pragma unroll 4
    for (int u = 0; u < 128; u++) {
        float4 fv = *(const float4*)&fT[u * FT_STRIDE + j0];
        float4 w0 = *(const float4*)&w_s[u * WS_STRIDE + vl0];
        float4 w1 = *(const float4*)&w_s[u * WS_STRIDE + vl0 + 4];
        float fj[4] = {fv.x, fv.y, fv.z, fv.w};
        float wv[8] = {w0.x, w0.y, w0.z, w0.w, w1.x, w1.y, w1.z, w1.w};
        #pragma unroll
        for (int a = 0; a < 4; a++)
            #pragma unroll
            for (int c = 0; c < 8; c++)
                acc[a][c] = fmaf(fj[a], wv[c], acc[a][c]);
    }

    #pragma unroll
    for (int a = 0; a < 4; a++) {
        float dj = d_s[j0 + a];
        #pragma unroll
        for (int c = 0; c < 8; c++)
            s_s[(j0 + a) * WS_STRIDE + vl0 + c] =
                fmaf(dj, wdot_s[vl0 + c], acc[a][c]);
    }
    __syncthreads();

    // ---- Phase 4: softmax over j + weighted sum.  4 lanes per v column. ----
    const int vv = tid >> 2;      // 0..63 local column
    const int r  = tid & 3;       // lane within column group
    const int u  = v0 + vv;       // global output index (u == v)

    float m = -1e30f;
    #pragma unroll 8
    for (int j = r; j < 128; j += 4)
        m = fmaxf(m, s_s[j * WS_STRIDE + vv]);
    m = fmaxf(m, __shfl_xor_sync(0xffffffffu, m, 1));
    m = fmaxf(m, __shfl_xor_sync(0xffffffffu, m, 2));

    float se = 0.f, o = 0.f;
    #pragma unroll 8
    for (int j = r; j < 128; j += 4) {
        float e = __expf(s_s[j * WS_STRIDE + vv] - m);
        se += e;
        o  = fmaf(e, fT[u * FT_STRIDE + j], o);
    }
    se += __shfl_xor_sync(0xffffffffu, se, 1);
    se += __shfl_xor_sync(0xffffffffu, se, 2);
    o  += __shfl_xor_sync(0xffffffffu, o, 1);
    o  += __shfl_xor_sync(0xffffffffu, o, 2);

    if (r == 0) out[b * 128 + u] = o / se;
}

extern "C" void kernel_launch(void* const* d_in, const int* in_sizes, int n_in,
                              void* d_out, int out_size)
{
    const float* input = (const float*)d_in[0];   // (64,128)
    const float* state = (const float*)d_in[1];   // (64,128,128)
    const float* w     = (const float*)d_in[2];   // (257,128); w[128:256] and b unused
    float* out = (float*)d_out;                   // (64,128)

    cudaFuncSetAttribute(rsa_kernel,
                         cudaFuncAttributeMaxDynamicSharedMemorySize, SMEM_BYTES);
    rsa_kernel<<<128, THREADS, SMEM_BYTES>>>(input, state, w, out);
}

// round 2
// speedup vs baseline: 1.3439x; 1.3439x over previous
#include <cuda_runtime.h>

// RSA_layer: B=64, U=W=128.
// Only output row i=127 is needed; softmax-constant terms (w_hj, bias) cancel.
// Per batch b:
//   f[j][u] = (u<127) ? state[b,j,u+1] : input[b,j]
//   d[j]    = f[127] . f[j]
//   s[j][v] = (f @ w_hi)[j][v] + d[j]*w_dot[v]
//   out[b][u] = sum_j f[j][u] * softmax_j(s[j][u])
//
// Grid: 64 batches x 2 v-halves = 128 CTAs, 512 threads (16 warps for latency hiding).

#define THREADS 512
#define FT_STRIDE 132
#define WS_STRIDE 68

static constexpr int SMEM_FLOATS = 128 * FT_STRIDE + 128 * WS_STRIDE * 2 + 128 + 64;
static constexpr int SMEM_BYTES = SMEM_FLOATS * 4;

__global__ __launch_bounds__(THREADS, 1)
void rsa_kernel(const float* __restrict__ input,
                const float* __restrict__ state,
                const float* __restrict__ w,
                float* __restrict__ out)
{
    extern __shared__ float sm[];

    const int b   = blockIdx.x >> 1;
    const int h   = blockIdx.x & 1;
    const int v0  = h * 64;           // global v/u offset of this CTA's half
    const int tid = threadIdx.x;

    float* fT     = sm;                          // [128 u][132] (col j)
    float* w_s    = fT  + 128 * FT_STRIDE;       // [128 u][68] (64 v cols)
    float* s_s    = w_s + 128 * WS_STRIDE;       // [128 j][68]
    float* d_s    = s_s + 128 * WS_STRIDE;       // [128]
    float* wdot_s = d_s + 128;                   // [64]

    const float* stateb = state + (size_t)b * 128 * 128;
    const float* inputb = input + b * 128;

    // ---- Phase 0: stage fT (transposed, shifted), w_hi half, wdot ----
    #pragma unroll 8
    for (int idx = tid; idx < 128 * 128; idx += THREADS) {
        int j = idx >> 7, u = idx & 127;
        float val = (u < 127) ? stateb[j * 128 + u + 1] : inputb[j];
        fT[u * FT_STRIDE + j] = val;
    }
    #pragma unroll 4
    for (int idx = tid; idx < 128 * 64; idx += THREADS) {
        int u = idx >> 6, vl = idx & 63;
        w_s[u * WS_STRIDE + vl] = w[u * 128 + v0 + vl];
    }
    if (tid < 64) wdot_s[tid] = w[256 * 128 + v0 + tid];
    __syncthreads();

    // ---- Phase 1: d[j] = f[127] . f[j]   (4 lanes per j; q read is a warp broadcast) ----
    {
        const int j = tid >> 2;        // 0..127
        const int r = tid & 3;
        float acc = 0.f;
        #pragma unroll 8
        for (int u = r; u < 128; u += 4)
            acc = fmaf(fT[u * FT_STRIDE + j], fT[u * FT_STRIDE + 127], acc);
        acc += __shfl_xor_sync(0xffffffffu, acc, 1);
        acc += __shfl_xor_sync(0xffffffffu, acc, 2);
        if (r == 0) d_s[j] = acc;
    }
    __syncthreads();

    // ---- Phase 2: s[j][v] = (f @ w_hi)[j][v] + d[j]*wdot[v] ----
    // 32(j-blocks) x 16(v-blocks) thread grid, each thread a 4(j) x 4(v) tile.
    const int ty  = tid >> 4;     // 0..31
    const int tx  = tid & 15;     // 0..15
    const int j0  = ty * 4;
    const int vl0 = tx * 4;

    float acc[4][4];
    #pragma unroll
    for (int a = 0; a < 4; a++)
        #pragma unroll
        for (int c = 0; c < 4; c++) acc[a][c] = 0.f;

    #pragma unroll 8
    for (int u = 0; u < 128; u++) {
        float4 fv = *(const float4*)&fT[u * FT_STRIDE + j0];
        float4 wv = *(const float4*)&w_s[u * WS_STRIDE + vl0];
        float fj[4] = {fv.x, fv.y, fv.z, fv.w};
        float wc[4] = {wv.x, wv.y, wv.z, wv.w};
        #pragma unroll
        for (int a = 0; a < 4; a++)
            #pragma unroll
            for (int c = 0; c < 4; c++)
                acc[a][c] = fmaf(fj[a], wc[c], acc[a][c]);
    }

    #pragma unroll
    for (int a = 0; a < 4; a++) {
        float dj = d_s[j0 + a];
        #pragma unroll
        for (int c = 0; c < 4; c++)
            s_s[(j0 + a) * WS_STRIDE + vl0 + c] =
                fmaf(dj, wdot_s[vl0 + c], acc[a][c]);
    }
    __syncthreads();

    // ---- Phase 3: softmax over j + weighted sum.  8 lanes per v column. ----
    const int vv = tid >> 3;      // 0..63 local column
    const int r  = tid & 7;       // lane within column group
    const int u  = v0 + vv;       // global output index (u == v)

    float m = -1e30f;
    #pragma unroll
    for (int j = r; j < 128; j += 8)
        m = fmaxf(m, s_s[j * WS_STRIDE + vv]);
    m = fmaxf(m, __shfl_xor_sync(0xffffffffu, m, 1));
    m = fmaxf(m, __shfl_xor_sync(0xffffffffu, m, 2));
    m = fmaxf(m, __shfl_xor_sync(0xffffffffu, m, 4));

    float se = 0.f, o = 0.f;
    #pragma unroll
    for (int j = r; j < 128; j += 8) {
        float e = __expf(s_s[j * WS_STRIDE + vv] - m);
        se += e;
        o  = fmaf(e, fT[u * FT_STRIDE + j], o);
    }
    se += __shfl_xor_sync(0xffffffffu, se, 1);
    se += __shfl_xor_sync(0xffffffffu, se, 2);
    se += __shfl_xor_sync(0xffffffffu, se, 4);
    o  += __shfl_xor_sync(0xffffffffu, o, 1);
    o  += __shfl_xor_sync(0xffffffffu, o, 2);
    o  += __shfl_xor_sync(0xffffffffu, o, 4);

    if (r == 0) out[b * 128 + u] = o / se;
}

extern "C" void kernel_launch(void* const* d_in, const int* in_sizes, int n_in,
                              void* d_out, int out_size)
{
    const float* input = (const float*)d_in[0];   // (64,128)
    const float* state = (const float*)d_in[1];   // (64,128,128)
    const float* w     = (const float*)d_in[2];   // (257,128); w[128:256] and b unused
    float* out = (float*)d_out;                   // (64,128)

    cudaFuncSetAttribute(rsa_kernel,
                         cudaFuncAttributeMaxDynamicSharedMemorySize, SMEM_BYTES);
    rsa_kernel<<<128, THREADS, SMEM_BYTES>>>(input, state, w, out);
}

// round 5
// speedup vs baseline: 1.6491x; 1.2271x over previous
#include <cuda_runtime.h>
#include <cuda_bf16.h>
#include <cstdint>

// RSA_layer: B=64, U=W=128.  out[b][u] = sum_j f[j][u]*softmax_j(s[j][u]),
//   s[j][v] = (f @ w_hi)[j][v] + (f[127].f[j]) * w_dot[v]
// GEMM on HMMA (mma.sync m16n8k16 bf16) with 3-term hi/lo split for fp32 accuracy.
// Grid: 64 batches x 2 v-halves = 128 CTAs, 256 threads (8 warps).

#define THREADS 256

#define A_STRIDE_B 272   // A row bytes (136 bf16): ldmatrix rows conflict-free
#define B_STRIDE_B 276   // Bt row bytes (138 bf16): odd word stride, conflict-free transpose stores
#define FT_STRIDE  133   // floats (odd) -> conflict-light transposed stores; scalar reads only
#define ST_STRIDE  132   // floats, 528B rows: float4-aligned

#define OFF_A_HI 0
#define OFF_A_LO (128 * A_STRIDE_B)                    // 34816
#define OFF_B_HI (2 * 128 * A_STRIDE_B)                // 69632
#define OFF_B_LO (OFF_B_HI + 64 * B_STRIDE_B)          // 87296
#define OFF_FT   (OFF_B_LO + 64 * B_STRIDE_B)          // 104960
#define OFF_ST   (OFF_FT + 128 * FT_STRIDE * 4)        // 173056 (16B aligned)
#define OFF_DS   (OFF_ST + 64 * ST_STRIDE * 4)         // 206848
#define OFF_WDOT (OFF_DS + 512)                        // 207360
#define SMEM_BYTES (OFF_WDOT + 256)                    // 207616

__device__ __forceinline__ uint32_t smem_u32(const void* p) {
    return (uint32_t)__cvta_generic_to_shared((void*)p);
}

__device__ __forceinline__ void ldmatrix_x4(uint32_t* a, uint32_t addr) {
    asm volatile("ldmatrix.sync.aligned.m8n8.x4.shared.b16 {%0,%1,%2,%3}, [%4];"
                 : "=r"(a[0]), "=r"(a[1]), "=r"(a[2]), "=r"(a[3]) : "r"(addr));
}

__device__ __forceinline__ void mma_16816(float* c, const uint32_t* a,
                                          uint32_t b0, uint32_t b1) {
    asm volatile(
        "mma.sync.aligned.m16n8k16.row.col.f32.bf16.bf16.f32 "
        "{%0,%1,%2,%3}, {%4,%5,%6,%7}, {%8,%9}, {%0,%1,%2,%3};"
        : "+f"(c[0]), "+f"(c[1]), "+f"(c[2]), "+f"(c[3])
        : "r"(a[0]), "r"(a[1]), "r"(a[2]), "r"(a[3]), "r"(b0), "r"(b1));
}

__global__ __launch_bounds__(THREADS, 1)
void rsa_kernel(const float* __restrict__ input,
                const float* __restrict__ state,
                const float* __restrict__ w,
                float* __restrict__ out)
{
    extern __shared__ char sm[];
    float* fT     = (float*)(sm + OFF_FT);     // fT[u][j] = f[j][u], fp32
    float* sT     = (float*)(sm + OFF_ST);     // sT[v][j]
    float* d_s    = (float*)(sm + OFF_DS);     // d[128]
    float* wdot_s = (float*)(sm + OFF_WDOT);   // wdot[64]

    const int tid = threadIdx.x;
    const int wid = tid >> 5;
    const int lid = tid & 31;
    const int b   = blockIdx.x >> 1;
    const int v0  = (blockIdx.x & 1) * 64;

    const float* stateb = state + (size_t)b * 128 * 128;
    const float* inputb = input + b * 128;

    // ---- Stage A = f[j][u] as bf16 hi/lo (row-major [j][u]) + fT fp32 [u][j] ----
    #pragma unroll 4
    for (int p = tid; p < 128 * 64; p += THREADS) {
        int j = p >> 6, up = p & 63, u = up << 1;
        float f0 = stateb[j * 128 + u + 1];
        float f1 = (up == 63) ? inputb[j] : stateb[j * 128 + u + 2];
        __nv_bfloat16 h0 = __float2bfloat16(f0), h1 = __float2bfloat16(f1);
        __nv_bfloat16 l0 = __float2bfloat16(f0 - __bfloat162float(h0));
        __nv_bfloat16 l1 = __float2bfloat16(f1 - __bfloat162float(h1));
        __nv_bfloat162 hp; hp.x = h0; hp.y = h1;
        __nv_bfloat162 lp; lp.x = l0; lp.y = l1;
        *(__nv_bfloat162*)(sm + OFF_A_HI + j * A_STRIDE_B + u * 2) = hp;
        *(__nv_bfloat162*)(sm + OFF_A_LO + j * A_STRIDE_B + u * 2) = lp;
        fT[u * FT_STRIDE + j]       = f0;
        fT[(u + 1) * FT_STRIDE + j] = f1;
    }
    // ---- Stage Bt[v][u] = w[u][v0+v] as bf16 hi/lo ----
    #pragma unroll 4
    for (int p = tid; p < 128 * 64; p += THREADS) {
        int u = p >> 6, vl = p & 63;
        float wv = w[u * 128 + v0 + vl];
        __nv_bfloat16 h = __float2bfloat16(wv);
        __nv_bfloat16 l = __float2bfloat16(wv - __bfloat162float(h));
        *(__nv_bfloat16*)(sm + OFF_B_HI + vl * B_STRIDE_B + u * 2) = h;
        *(__nv_bfloat16*)(sm + OFF_B_LO + vl * B_STRIDE_B + u * 2) = l;
    }
    if (tid < 64) wdot_s[tid] = w[256 * 128 + v0 + tid];
    __syncthreads();

    // ---- d[j] = f[127] . f[j]  (2 lanes per j) ----
    {
        const int j = tid >> 1, r = tid & 1;
        float acc = 0.f;
        #pragma unroll 8
        for (int u = r; u < 128; u += 2)
            acc = fmaf(fT[u * FT_STRIDE + j], fT[u * FT_STRIDE + 127], acc);
        acc += __shfl_xor_sync(0xffffffffu, acc, 1);
        if (r == 0) d_s[j] = acc;
    }
    __syncthreads();

    // ---- GEMM: warp tile = 32 j x 32 v (2 m-tiles x 4 n-tiles), K=128, 3 splits ----
    {
        const int wj = (wid & 3) * 32;          // j block
        const int wv = (wid >> 2) * 32;         // local v block

        float acc[2][4][4];
        #pragma unroll
        for (int mt = 0; mt < 2; mt++)
            #pragma unroll
            for (int n = 0; n < 4; n++)
                #pragma unroll
                for (int c = 0; c < 4; c++) acc[mt][n][c] = 0.f;

        const int lrow  = lid & 15;
        const int lcolb = (lid >> 4) * 16;      // 8 bf16 = 16 bytes
        const int bn = lid >> 2;                // n within 8
        const int bk = (lid & 3) * 4;           // k-pair byte offset

        const uint32_t a_off[3] = {OFF_A_HI, OFF_A_LO, OFF_A_HI};
        const uint32_t b_off[3] = {OFF_B_HI, OFF_B_HI, OFF_B_LO};
        const uint32_t smb = smem_u32(sm);

        #pragma unroll
        for (int s = 0; s < 3; s++) {
            const uint32_t abase = smb + a_off[s]
                                 + (uint32_t)(wj + lrow) * A_STRIDE_B + lcolb;
            const char* bbase = sm + b_off[s];
            #pragma unroll
            for (int k = 0; k < 8; k++) {
                uint32_t a0[4], a1[4];
                ldmatrix_x4(a0, abase + k * 32);
                ldmatrix_x4(a1, abase + 16 * A_STRIDE_B + k * 32);
                #pragma unroll
                for (int n = 0; n < 4; n++) {
                    const char* bp = bbase + (wv + n * 8 + bn) * B_STRIDE_B + k * 32 + bk;
                    uint32_t b0 = *(const uint32_t*)bp;
                    uint32_t b1 = *(const uint32_t*)(bp + 16);
                    mma_16816(acc[0][n], a0, b0, b1);
                    mma_16816(acc[1][n], a1, b0, b1);
                }
            }
        }

        // ---- Epilogue: fold d[j]*wdot[v], store transposed sT[v][j] ----
        const int er = lid >> 2;
        const int ec = (lid & 3) * 2;
        #pragma unroll
        for (int mt = 0; mt < 2; mt++) {
            int j0 = wj + mt * 16 + er;
            float dj0 = d_s[j0], dj8 = d_s[j0 + 8];
            #pragma unroll
            for (int n = 0; n < 4; n++) {
                int v = wv + n * 8 + ec;
                float w0 = wdot_s[v], w1 = wdot_s[v + 1];
                sT[v * ST_STRIDE + j0]           = fmaf(dj0, w0, acc[mt][n][0]);
                sT[(v + 1) * ST_STRIDE + j0]     = fmaf(dj0, w1, acc[mt][n][1]);
                sT[v * ST_STRIDE + j0 + 8]       = fmaf(dj8, w0, acc[mt][n][2]);
                sT[(v + 1) * ST_STRIDE + j0 + 8] = fmaf(dj8, w1, acc[mt][n][3]);
            }
        }
    }
    __syncthreads();

    // ---- Softmax over j + weighted sum.  4 lanes / column, 32 j each.
    //      Lane phase staggered by r: scalar f-loads hit all 32 banks. ----
    {
        const int vv = tid >> 2;           // 0..63 local column
        const int r  = tid & 3;
        const int j0 = r * 32;
        const float* srow = sT + vv * ST_STRIDE + j0;
        const float* frow = fT + (v0 + vv) * FT_STRIDE + j0;

        float m = -1e30f;
        #pragma unroll
        for (int t = 0; t < 8; t++) {
            int tt = (t + 2 * r) & 7;
            float4 v4 = *(const float4*)(srow + 4 * tt);
            m = fmaxf(m, fmaxf(fmaxf(v4.x, v4.y), fmaxf(v4.z, v4.w)));
        }
        m = fmaxf(m, __shfl_xor_sync(0xffffffffu, m, 1));
        m = fmaxf(m, __shfl_xor_sync(0xffffffffu, m, 2));

        float se = 0.f, o = 0.f;
        #pragma unroll
        for (int t = 0; t < 8; t++) {
            int tt = (t + 2 * r) & 7;
            float4 v4 = *(const float4*)(srow + 4 * tt);
            float e0 = __expf(v4.x - m), e1 = __expf(v4.y - m);
            float e2 = __expf(v4.z - m), e3 = __expf(v4.w - m);
            se += (e0 + e1) + (e2 + e3);
            o = fmaf(e0, frow[4 * tt],     o);
            o = fmaf(e1, frow[4 * tt + 1], o);
            o = fmaf(e2, frow[4 * tt + 2], o);
            o = fmaf(e3, frow[4 * tt + 3], o);
        }
        se += __shfl_xor_sync(0xffffffffu, se, 1);
        se += __shfl_xor_sync(0xffffffffu, se, 2);
        o  += __shfl_xor_sync(0xffffffffu, o, 1);
        o  += __shfl_xor_sync(0xffffffffu, o, 2);

        if (r == 0) out[b * 128 + v0 + vv] = o / se;
    }
}

extern "C" void kernel_launch(void* const* d_in, const int* in_sizes, int n_in,
                              void* d_out, int out_size)
{
    const float* input = (const float*)d_in[0];   // (64,128)
    const float* state = (const float*)d_in[1];   // (64,128,128)
    const float* w     = (const float*)d_in[2];   // (257,128); w[128:256], b unused
    float* out = (float*)d_out;                   // (64,128)

    cudaFuncSetAttribute(rsa_kernel,
                         cudaFuncAttributeMaxDynamicSharedMemorySize, SMEM_BYTES);
    rsa_kernel<<<128, THREADS, SMEM_BYTES>>>(input, state, w, out);
}

// round 6
// speedup vs baseline: 1.8020x; 1.0927x over previous
#include <cuda_runtime.h>
#include <cuda_bf16.h>
#include <cstdint>

// RSA_layer: B=64, U=W=128.  out[b][u] = sum_j f[j][u]*softmax_j(s[j][u]),
//   s[j][v] = (f @ w_hi)[j][v] + (f[127].f[j]) * w_dot[v]
// GEMM on HMMA (mma.sync m16n8k16 bf16) with 3-term hi/lo split for fp32 accuracy.
// Grid: 64 batches x 2 v-halves = 128 CTAs, 512 threads (16 warps).

#define THREADS 512

#define A_STRIDE_B 272   // A row bytes (136 bf16): ldmatrix rows conflict-free
#define B_STRIDE_B 276   // Bt row bytes (138 bf16): odd word stride, conflict-free transpose stores
#define FT_STRIDE  133   // floats (odd) -> conflict-light transposed stores; scalar reads only
#define ST_STRIDE  132   // floats, 528B rows: float4-aligned

#define OFF_A_HI 0
#define OFF_A_LO (128 * A_STRIDE_B)                    // 34816
#define OFF_B_HI (2 * 128 * A_STRIDE_B)                // 69632
#define OFF_B_LO (OFF_B_HI + 64 * B_STRIDE_B)          // 87296
#define OFF_FT   (OFF_B_LO + 64 * B_STRIDE_B)          // 104960
#define OFF_ST   (OFF_FT + 128 * FT_STRIDE * 4)        // 173056 (16B aligned)
#define OFF_DS   (OFF_ST + 64 * ST_STRIDE * 4)         // 206848
#define OFF_WDOT (OFF_DS + 512)                        // 207360
#define SMEM_BYTES (OFF_WDOT + 256)                    // 207616

__device__ __forceinline__ uint32_t smem_u32(const void* p) {
    return (uint32_t)__cvta_generic_to_shared((void*)p);
}

__device__ __forceinline__ void ldmatrix_x4(uint32_t* a, uint32_t addr) {
    asm volatile("ldmatrix.sync.aligned.m8n8.x4.shared.b16 {%0,%1,%2,%3}, [%4];"
                 : "=r"(a[0]), "=r"(a[1]), "=r"(a[2]), "=r"(a[3]) : "r"(addr));
}

__device__ __forceinline__ void mma_16816(float* c, const uint32_t* a,
                                          uint32_t b0, uint32_t b1) {
    asm volatile(
        "mma.sync.aligned.m16n8k16.row.col.f32.bf16.bf16.f32 "
        "{%0,%1,%2,%3}, {%4,%5,%6,%7}, {%8,%9}, {%0,%1,%2,%3};"
        : "+f"(c[0]), "+f"(c[1]), "+f"(c[2]), "+f"(c[3])
        : "r"(a[0]), "r"(a[1]), "r"(a[2]), "r"(a[3]), "r"(b0), "r"(b1));
}

__global__ __launch_bounds__(THREADS, 1)
void rsa_kernel(const float* __restrict__ input,
                const float* __restrict__ state,
                const float* __restrict__ w,
                float* __restrict__ out)
{
    extern __shared__ char sm[];
    float* fT     = (float*)(sm + OFF_FT);     // fT[u][j] = f[j][u], fp32
    float* sT     = (float*)(sm + OFF_ST);     // sT[v][j]
    float* d_s    = (float*)(sm + OFF_DS);     // d[128]
    float* wdot_s = (float*)(sm + OFF_WDOT);   // wdot[64]

    const int tid = threadIdx.x;
    const int wid = tid >> 5;
    const int lid = tid & 31;
    const int b   = blockIdx.x >> 1;
    const int v0  = (blockIdx.x & 1) * 64;

    const float* stateb = state + (size_t)b * 128 * 128;
    const float* inputb = input + b * 128;

    // ---- Stage A = f[j][u] as bf16 hi/lo (row-major [j][u]) + fT fp32 [u][j] ----
    #pragma unroll 4
    for (int p = tid; p < 128 * 64; p += THREADS) {
        int j = p >> 6, up = p & 63, u = up << 1;
        float f0 = stateb[j * 128 + u + 1];
        float f1 = (up == 63) ? inputb[j] : stateb[j * 128 + u + 2];
        __nv_bfloat16 h0 = __float2bfloat16(f0), h1 = __float2bfloat16(f1);
        __nv_bfloat16 l0 = __float2bfloat16(f0 - __bfloat162float(h0));
        __nv_bfloat16 l1 = __float2bfloat16(f1 - __bfloat162float(h1));
        __nv_bfloat162 hp; hp.x = h0; hp.y = h1;
        __nv_bfloat162 lp; lp.x = l0; lp.y = l1;
        *(__nv_bfloat162*)(sm + OFF_A_HI + j * A_STRIDE_B + u * 2) = hp;
        *(__nv_bfloat162*)(sm + OFF_A_LO + j * A_STRIDE_B + u * 2) = lp;
        fT[u * FT_STRIDE + j]       = f0;
        fT[(u + 1) * FT_STRIDE + j] = f1;
    }
    // ---- Stage Bt[v][u] = w[u][v0+v] as bf16 hi/lo ----
    #pragma unroll 4
    for (int p = tid; p < 128 * 64; p += THREADS) {
        int u = p >> 6, vl = p & 63;
        float wv = w[u * 128 + v0 + vl];
        __nv_bfloat16 h = __float2bfloat16(wv);
        __nv_bfloat16 l = __float2bfloat16(wv - __bfloat162float(h));
        *(__nv_bfloat16*)(sm + OFF_B_HI + vl * B_STRIDE_B + u * 2) = h;
        *(__nv_bfloat16*)(sm + OFF_B_LO + vl * B_STRIDE_B + u * 2) = l;
    }
    if (tid < 64) wdot_s[tid] = w[256 * 128 + v0 + tid];
    __syncthreads();

    // ---- d[j] = f[127] . f[j]  (4 lanes per j) ----
    {
        const int j = tid >> 2, r = tid & 3;
        float acc = 0.f;
        #pragma unroll 8
        for (int u = r; u < 128; u += 4)
            acc = fmaf(fT[u * FT_STRIDE + j], fT[u * FT_STRIDE + 127], acc);
        acc += __shfl_xor_sync(0xffffffffu, acc, 1);
        acc += __shfl_xor_sync(0xffffffffu, acc, 2);
        if (r == 0) d_s[j] = acc;
    }
    __syncthreads();

    // ---- GEMM: warp tile = 32 j x 16 v (2 m-tiles x 2 n-tiles), K=128, 3 splits ----
    {
        const int wj = (wid & 3) * 32;          // j block
        const int wv = (wid >> 2) * 16;         // local v block

        float acc[2][2][4];
        #pragma unroll
        for (int mt = 0; mt < 2; mt++)
            #pragma unroll
            for (int n = 0; n < 2; n++)
                #pragma unroll
                for (int c = 0; c < 4; c++) acc[mt][n][c] = 0.f;

        const int lrow  = lid & 15;
        const int lcolb = (lid >> 4) * 16;      // 8 bf16 = 16 bytes
        const int bn = lid >> 2;                // n within 8
        const int bk = (lid & 3) * 4;           // k-pair byte offset

        const uint32_t a_off[3] = {OFF_A_HI, OFF_A_LO, OFF_A_HI};
        const uint32_t b_off[3] = {OFF_B_HI, OFF_B_HI, OFF_B_LO};
        const uint32_t smb = smem_u32(sm);

        #pragma unroll
        for (int s = 0; s < 3; s++) {
            const uint32_t abase = smb + a_off[s]
                                 + (uint32_t)(wj + lrow) * A_STRIDE_B + lcolb;
            const char* bbase = sm + b_off[s];
            #pragma unroll
            for (int k = 0; k < 8; k++) {
                uint32_t a0[4], a1[4];
                ldmatrix_x4(a0, abase + k * 32);
                ldmatrix_x4(a1, abase + 16 * A_STRIDE_B + k * 32);
                #pragma unroll
                for (int n = 0; n < 2; n++) {
                    const char* bp = bbase + (wv + n * 8 + bn) * B_STRIDE_B + k * 32 + bk;
                    uint32_t b0 = *(const uint32_t*)bp;
                    uint32_t b1 = *(const uint32_t*)(bp + 16);
                    mma_16816(acc[0][n], a0, b0, b1);
                    mma_16816(acc[1][n], a1, b0, b1);
                }
            }
        }

        // ---- Epilogue: fold d[j]*wdot[v], store transposed sT[v][j] ----
        const int er = lid >> 2;
        const int ec = (lid & 3) * 2;
        #pragma unroll
        for (int mt = 0; mt < 2; mt++) {
            int j0 = wj + mt * 16 + er;
            float dj0 = d_s[j0], dj8 = d_s[j0 + 8];
            #pragma unroll
            for (int n = 0; n < 2; n++) {
                int v = wv + n * 8 + ec;
                float w0 = wdot_s[v], w1 = wdot_s[v + 1];
                sT[v * ST_STRIDE + j0]           = fmaf(dj0, w0, acc[mt][n][0]);
                sT[(v + 1) * ST_STRIDE + j0]     = fmaf(dj0, w1, acc[mt][n][1]);
                sT[v * ST_STRIDE + j0 + 8]       = fmaf(dj8, w0, acc[mt][n][2]);
                sT[(v + 1) * ST_STRIDE + j0 + 8] = fmaf(dj8, w1, acc[mt][n][3]);
            }
        }
    }
    __syncthreads();

    // ---- Softmax over j + weighted sum.  8 lanes / column, 16 j each.
    //      float4 sT reads phase-staggered by (t+r)&3 (<=2-way conflicts). ----
    {
        const int vv = tid >> 3;           // 0..63 local column
        const int r  = tid & 7;
        const int j0 = r * 16;
        const float* srow = sT + vv * ST_STRIDE + j0;
        const float* frow = fT + (v0 + vv) * FT_STRIDE + j0;

        float m = -1e30f;
        #pragma unroll
        for (int t = 0; t < 4; t++) {
            int tt = (t + r) & 3;
            float4 v4 = *(const float4*)(srow + 4 * tt);
            m = fmaxf(m, fmaxf(fmaxf(v4.x, v4.y), fmaxf(v4.z, v4.w)));
        }
        m = fmaxf(m, __shfl_xor_sync(0xffffffffu, m, 1));
        m = fmaxf(m, __shfl_xor_sync(0xffffffffu, m, 2));
        m = fmaxf(m, __shfl_xor_sync(0xffffffffu, m, 4));

        float se = 0.f, o = 0.f;
        #pragma unroll
        for (int t = 0; t < 4; t++) {
            int tt = (t + r) & 3;
            float4 v4 = *(const float4*)(srow + 4 * tt);
            float e0 = __expf(v4.x - m), e1 = __expf(v4.y - m);
            float e2 = __expf(v4.z - m), e3 = __expf(v4.w - m);
            se += (e0 + e1) + (e2 + e3);
            o = fmaf(e0, frow[4 * tt],     o);
            o = fmaf(e1, frow[4 * tt + 1], o);
            o = fmaf(e2, frow[4 * tt + 2], o);
            o = fmaf(e3, frow[4 * tt + 3], o);
        }
        se += __shfl_xor_sync(0xffffffffu, se, 1);
        se += __shfl_xor_sync(0xffffffffu, se, 2);
        se += __shfl_xor_sync(0xffffffffu, se, 4);
        o  += __shfl_xor_sync(0xffffffffu, o, 1);
        o  += __shfl_xor_sync(0xffffffffu, o, 2);
        o  += __shfl_xor_sync(0xffffffffu, o, 4);

        if (r == 0) out[b * 128 + v0 + vv] = o / se;
    }
}

extern "C" void kernel_launch(void* const* d_in, const int* in_sizes, int n_in,
                              void* d_out, int out_size)
{
    const float* input = (const float*)d_in[0];   // (64,128)
    const float* state = (const float*)d_in[1];   // (64,128,128)
    const float* w     = (const float*)d_in[2];   // (257,128); w[128:256], b unused
    float* out = (float*)d_out;                   // (64,128)

    cudaFuncSetAttribute(rsa_kernel,
                         cudaFuncAttributeMaxDynamicSharedMemorySize, SMEM_BYTES);
    rsa_kernel<<<128, THREADS, SMEM_BYTES>>>(input, state, w, out);
}